// round 8
// baseline (speedup 1.0000x reference)
#include <cuda_runtime.h>
#include <cuda_fp16.h>
#include <cstdint>

#define B_ 8
#define D_ 128
#define N_ 2048
#define BM 128
#define BN 128
#define NITER (N_ / BN)

__device__ __align__(16) __half g_Qh[B_ * D_ * N_];  // [b][d][n]
__device__ __align__(16) __half g_Kh[B_ * D_ * N_];  // [b][d][m]
__device__ __align__(16) __half g_Vh[B_ * D_ * N_];  // [b][v][n]

__device__ __forceinline__ uint32_t s2u(const void* p) {
    uint32_t a;
    asm("{ .reg .u64 t; cvta.to.shared.u64 t, %1; cvt.u32.u64 %0, t; }" : "=r"(a) : "l"(p));
    return a;
}

#define CPA16(dst, src) \
    asm volatile("cp.async.cg.shared.global [%0], [%1], 16;" :: "r"(dst), "l"(src))
#define CPA_COMMIT() asm volatile("cp.async.commit_group;" ::: "memory")
#define CPA_WAIT0()  asm volatile("cp.async.wait_group 0;" ::: "memory")

__device__ __forceinline__ void ldmx4(uint32_t* r, uint32_t addr) {
    asm volatile("ldmatrix.sync.aligned.m8n8.x4.shared.b16 {%0,%1,%2,%3}, [%4];"
        : "=r"(r[0]), "=r"(r[1]), "=r"(r[2]), "=r"(r[3]) : "r"(addr));
}
__device__ __forceinline__ void ldmx4t(uint32_t* r, uint32_t addr) {
    asm volatile("ldmatrix.sync.aligned.m8n8.x4.trans.shared.b16 {%0,%1,%2,%3}, [%4];"
        : "=r"(r[0]), "=r"(r[1]), "=r"(r[2]), "=r"(r[3]) : "r"(addr));
}
__device__ __forceinline__ void mma16816(float* d, const uint32_t* a, const uint32_t* b) {
    asm volatile("mma.sync.aligned.m16n8k16.row.col.f32.f16.f16.f32 "
        "{%0,%1,%2,%3}, {%4,%5,%6,%7}, {%8,%9}, {%0,%1,%2,%3};"
        : "+f"(d[0]), "+f"(d[1]), "+f"(d[2]), "+f"(d[3])
        : "r"(a[0]), "r"(a[1]), "r"(a[2]), "r"(a[3]), "r"(b[0]), "r"(b[1]));
}

// sigmoid(x/sqrt(128)) = 0.5*tanh(x/(2*sqrt(128))) + 0.5  (single MUFU)
__device__ __forceinline__ float sigf(float x) {
    const float c = 0.5f * 0.08838834764831845f;
    float t;
    asm("tanh.approx.f32 %0, %1;" : "=f"(t) : "f"(x * c));
    return fmaf(t, 0.5f, 0.5f);
}
__device__ __forceinline__ uint32_t packh2(float a, float b) {
    uint32_t r;
    asm("cvt.rn.f16x2.f32 %0, %1, %2;" : "=r"(r) : "f"(b), "f"(a));
    return r;
}

// smem: K 32KB @0 | Q[2] 64KB @32K | V[2] 64KB @96K | P 32KB @160K
#define SM_K 0
#define SM_Q 32768
#define SM_V 98304
#define SM_P 163840
#define SMEM_TOTAL 196608

__global__ __launch_bounds__(256, 1)
void sigattn_hmma(float* __restrict__ O) {
    extern __shared__ char sm[];
    const uint32_t sb = s2u(sm);
    const int tid = threadIdx.x, w = tid >> 5, lane = tid & 31;
    const int b = blockIdx.y, m0 = blockIdx.x * BM;
    const int g = lane >> 3, sx = lane & 7;
    const int mg = w & 3;        // m-group: m32 rows mg*32..
    const int vg = w >> 2;       // n-group (phase1) / v-group (phase2): 64-slice

    auto loadQV = [&](int it, int buf) {
        const int n0 = it * BN;
        const uint32_t qd = sb + SM_Q + buf * 32768;
        const uint32_t vd = sb + SM_V + buf * 32768;
#pragma unroll
        for (int r = 0; r < 8; r++) {
            int i = tid + r * 256;
            int d = i >> 4, c = i & 15;
            uint32_t off = (uint32_t)(d * 256 + ((c ^ (d & 7)) << 4));
            CPA16(qd + off, (const char*)g_Qh + ((size_t)(b * D_ + d) * N_ + n0 + c * 8) * 2);
            CPA16(vd + off, (const char*)g_Vh + ((size_t)(b * D_ + d) * N_ + n0 + c * 8) * 2);
        }
    };

    // prologue: K tile [d][m0..m0+127] + (Q,V)(0)
#pragma unroll
    for (int r = 0; r < 8; r++) {
        int i = tid + r * 256;
        int d = i >> 4, c = i & 15;
        CPA16(sb + SM_K + d * 256 + ((c ^ (d & 7)) << 4),
              (const char*)g_Kh + ((size_t)(b * D_ + d) * N_ + m0 + c * 8) * 2);
    }
    loadQV(0, 0);
    CPA_COMMIT();
    CPA_WAIT0();
    __syncthreads();

    // ---- resident K frags: A m16k16 for m = mg*32 + mf*16, all 8 k-chunks ----
    uint32_t kf[2][8][4];
    {
        const int drow = (g >> 1) * 8 + sx;
#pragma unroll
        for (int mf = 0; mf < 2; mf++) {
            const uint32_t coff =
                (uint32_t)((((4 * mg + 2 * mf + (g & 1)) ^ sx) & 15) << 4);
#pragma unroll
            for (int kc = 0; kc < 8; kc++)
                ldmx4t(kf[mf][kc], sb + SM_K + (uint32_t)((kc * 16 + drow) * 256) + coff);
        }
    }

    float ob[16][4];
#pragma unroll
    for (int i = 0; i < 16; i++)
#pragma unroll
        for (int j = 0; j < 4; j++) ob[i][j] = 0.0f;

    const int qrow  = (g & 1) * 8 + sx;   // Q trans-tile d-row offset
    const int qcoff = g >> 1;             // Q chunk parity
    const int rL    = sx + ((lane >> 4) << 3);  // V ldmatrix row
    const int cp_   = g & 1;              // V chunk parity
    const int prow0 = mg * 32 + (lane >> 2);    // P store row (c0/c1)
    const int pcol0 = (lane & 3) * 2;           // P store col within n8

    for (int it = 0; it < NITER; it++) {
        const int buf = it & 1;
        if (it + 1 < NITER) { loadQV(it + 1, buf ^ 1); CPA_COMMIT(); }

        const uint32_t qbuf = sb + SM_Q + buf * 32768;
        const uint32_t vbuf = sb + SM_V + buf * 32768;

        // ===== Phase 1: S[m32, n64-slice vg] -> sigmoid -> P smem =====
#pragma unroll
        for (int h = 0; h < 2; h++) {           // two n32 sub-chunks
            const int ci = vg * 2 + h;          // n32 chunk index in 0..3
            float sc[2][4][4];
#pragma unroll
            for (int mf = 0; mf < 2; mf++)
#pragma unroll
                for (int nj = 0; nj < 4; nj++)
#pragma unroll
                    for (int q = 0; q < 4; q++) sc[mf][nj][q] = 0.0f;

#pragma unroll
            for (int kc = 0; kc < 8; kc++) {
                uint32_t qb8[8];
                const uint32_t qr = qbuf + (uint32_t)((kc * 16 + qrow) * 256);
                ldmx4t(&qb8[0], qr + (uint32_t)((((4 * ci + qcoff)     ^ sx) & 15) << 4));
                ldmx4t(&qb8[4], qr + (uint32_t)((((4 * ci + 2 + qcoff) ^ sx) & 15) << 4));
#pragma unroll
                for (int mf = 0; mf < 2; mf++)
#pragma unroll
                    for (int nj = 0; nj < 4; nj++)
                        mma16816(sc[mf][nj], kf[mf][kc], &qb8[nj * 2]);
            }

            // sigmoid + pack + store P[m32, n32] (swizzled fp16 rows of 256B)
#pragma unroll
            for (int mf = 0; mf < 2; mf++) {
                const int r0 = prow0 + mf * 16;
#pragma unroll
                for (int nj = 0; nj < 4; nj++) {
                    const int n = ci * 32 + nj * 8 + pcol0;
                    const uint32_t a0 = (uint32_t)(r0 * 256 +
                        ((((n >> 3) ^ (r0 & 7)) & 15) << 4) + (n & 7) * 2);
                    const int r1 = r0 + 8;
                    const uint32_t a1 = (uint32_t)(r1 * 256 +
                        ((((n >> 3) ^ (r1 & 7)) & 15) << 4) + (n & 7) * 2);
                    *(uint32_t*)(sm + SM_P + a0) = packh2(sigf(sc[mf][nj][0]), sigf(sc[mf][nj][1]));
                    *(uint32_t*)(sm + SM_P + a1) = packh2(sigf(sc[mf][nj][2]), sigf(sc[mf][nj][3]));
                }
            }
        }
        __syncthreads();   // P complete

        // ===== Phase 2: O[m32, v64-slice vg] += P[m32,:] . V^T =====
#pragma unroll
        for (int kc = 0; kc < 8; kc++) {        // k = n16 chunks
            uint32_t pa[2][4];
#pragma unroll
            for (int mf = 0; mf < 2; mf++) {
                const int pr = mg * 32 + mf * 16 + (g & 1) * 8 + sx;
                const uint32_t pa_addr = sb + SM_P + (uint32_t)(pr * 256 +
                    ((((kc * 2 + (g >> 1)) ^ (pr & 7)) & 15) << 4));
                ldmx4(pa[mf], pa_addr);
            }
            const uint32_t swz = (uint32_t)((((2 * kc + cp_) ^ sx) & 15) << 4);
            const uint32_t vb0 = vbuf + (uint32_t)(vg * 16384 + rL * 256) + swz;
#pragma unroll
            for (int j = 0; j < 4; j++) {       // v16 blocks within v64
                uint32_t vb[4];
                ldmx4(vb, vb0 + (uint32_t)(j * 4096));
#pragma unroll
                for (int mf = 0; mf < 2; mf++) {
                    mma16816(ob[mf * 8 + j * 2],     pa[mf], &vb[0]);
                    mma16816(ob[mf * 8 + j * 2 + 1], pa[mf], &vb[2]);
                }
            }
        }

        CPA_WAIT0();
        __syncthreads();   // P consumed; next tiles ready
    }

    // ---- epilogue: O[m32(mg), v64(vg)] -> O[b][v][m0+m] ----
    float* Ob = O + (size_t)b * D_ * N_ + m0;
    const int mr = mg * 32 + (lane >> 2);
    const int c0 = 2 * (lane & 3);
#pragma unroll
    for (int mf = 0; mf < 2; mf++)
#pragma unroll
        for (int j2 = 0; j2 < 8; j2++) {
            const int v = vg * 64 + j2 * 8 + c0;
            const int m = mr + mf * 16;
            float* p = &ob[mf * 8 + j2][0];
            Ob[(size_t)v * N_ + m]           = p[0];
            Ob[(size_t)(v + 1) * N_ + m]     = p[1];
            Ob[(size_t)v * N_ + m + 8]       = p[2];
            Ob[(size_t)(v + 1) * N_ + m + 8] = p[3];
        }
}

// ---- preprocess: pure fp32 -> fp16 cast, native layouts ----
__global__ void prep_cast(const float* __restrict__ Q, const float* __restrict__ K,
                          const float* __restrict__ V) {
    int i = blockIdx.x * 256 + threadIdx.x;
    const float* src = (blockIdx.y == 0) ? Q : (blockIdx.y == 1) ? K : V;
    __half* dst = (blockIdx.y == 0) ? g_Qh : (blockIdx.y == 1) ? g_Kh : g_Vh;
    float4 v = ((const float4*)src)[i];
    __half2* o = (__half2*)dst;
    o[2 * i]     = __floats2half2_rn(v.x, v.y);
    o[2 * i + 1] = __floats2half2_rn(v.z, v.w);
}

extern "C" void kernel_launch(void* const* d_in, const int* in_sizes, int n_in,
                              void* d_out, int out_size) {
    const float* Q = (const float*)d_in[0];
    const float* K = (const float*)d_in[1];
    const float* V = (const float*)d_in[2];
    float* O = (float*)d_out;

    prep_cast<<<dim3((B_ * D_ * N_ / 4) / 256, 3), 256>>>(Q, K, V);

    cudaFuncSetAttribute(sigattn_hmma, cudaFuncAttributeMaxDynamicSharedMemorySize, SMEM_TOTAL);
    sigattn_hmma<<<dim3(N_ / BM, B_), 256, SMEM_TOTAL>>>(O);
}